// round 1
// baseline (speedup 1.0000x reference)
#include <cuda_runtime.h>
#include <cuda_bf16.h>
#include <cstdint>

// Problem constants
#define Bq 2
#define Sq 2048
#define Hq 1024
#define NHq 16
#define HDq 64
#define Mq (Bq * Sq)   // 4096

// ---------------------------------------------------------------------------
// Scratch (device globals — no allocation allowed)
// ---------------------------------------------------------------------------
__device__ float g_xln[(size_t)Mq * Hq];                       // 16 MB
__device__ float g_q[(size_t)Bq * NHq * Sq * HDq];             // 16 MB
__device__ float g_k[(size_t)Bq * NHq * Sq * HDq];             // 16 MB
__device__ float g_v[(size_t)Bq * NHq * Sq * HDq];             // 16 MB
__device__ float g_sc[(size_t)Bq * NHq * Sq * Sq];             // 512 MB
__device__ float g_ctx[(size_t)Mq * Hq];                       // 16 MB

// ---------------------------------------------------------------------------
// LayerNorm: one block per row (4096 rows, H=1024), 256 threads x 4 floats
// ---------------------------------------------------------------------------
__global__ __launch_bounds__(256) void ln_k(const float* __restrict__ x,
                                            const float* __restrict__ gamma,
                                            const float* __restrict__ beta,
                                            float* __restrict__ out) {
    const int row = blockIdx.x;
    const int tid = threadIdx.x;
    const float* xr = x + (size_t)row * Hq;

    float4 v = reinterpret_cast<const float4*>(xr)[tid];
    float s  = v.x + v.y + v.z + v.w;
    float ss = v.x * v.x + v.y * v.y + v.z * v.z + v.w * v.w;

    __shared__ float red[256];
    // sum
    red[tid] = s; __syncthreads();
    for (int off = 128; off > 0; off >>= 1) {
        if (tid < off) red[tid] += red[tid + off];
        __syncthreads();
    }
    const float mean = red[0] * (1.0f / Hq);
    __syncthreads();
    // sum of squares
    red[tid] = ss; __syncthreads();
    for (int off = 128; off > 0; off >>= 1) {
        if (tid < off) red[tid] += red[tid + off];
        __syncthreads();
    }
    const float var  = red[0] * (1.0f / Hq) - mean * mean;
    const float rstd = rsqrtf(var + 1e-12f);

    float4 g = reinterpret_cast<const float4*>(gamma)[tid];
    float4 b = reinterpret_cast<const float4*>(beta)[tid];
    float4 o;
    o.x = (v.x - mean) * rstd * g.x + b.x;
    o.y = (v.y - mean) * rstd * g.y + b.y;
    o.z = (v.z - mean) * rstd * g.z + b.z;
    o.w = (v.w - mean) * rstd * g.w + b.w;
    reinterpret_cast<float4*>(out + (size_t)row * Hq)[tid] = o;
}

// ---------------------------------------------------------------------------
// Generic tiled fp32 GEMM.
//   TRANSB=true : C = A[M,K] * B[N,K]^T   (both K-major, "NT")
//   TRANSB=false: C = A[M,K] * B[K,N]     ("NN")
// MODE:
//   0: out-proj:   C[m,n] = acc + bias[n] + extra[m*N+n]           (plain layout)
//   1: QKV proj:   v = (acc + bias[n]) * scale -> head layout [B,NH,S,HD]
//   2: scores:     v = acc + mask[(bz/NH)*S + n] -> C + bz*strideC (plain layout)
//   3: ctx (PV):   v = acc -> ctx[b, m, h*HD + n]   with b=bz/NH, h=bz%NH
// ---------------------------------------------------------------------------
template <int BM, int BN, int BK, int TM, int TN, bool TRANSB, int MODE>
__global__ __launch_bounds__((BM / TM) * (BN / TN))
void gemm_k(const float* __restrict__ A, const float* __restrict__ B,
            const float* __restrict__ bias, const float* __restrict__ extra,
            float* __restrict__ C, int Mdim, int Ndim, int Kdim,
            long strideA, long strideB, long strideC, float scale) {
    constexpr int THREADS = (BM / TM) * (BN / TN);
    const int tid = threadIdx.x;
    const int tx  = tid % (BN / TN);
    const int ty  = tid / (BN / TN);
    const int bz  = blockIdx.z;

    A += (size_t)bz * strideA;
    B += (size_t)bz * strideB;

    __shared__ float As[BK][BM + 4];
    __shared__ float Bs[BK][BN + 4];

    float acc[TM][TN];
#pragma unroll
    for (int i = 0; i < TM; ++i)
#pragma unroll
        for (int j = 0; j < TN; ++j) acc[i][j] = 0.0f;

    const int m0 = blockIdx.y * BM;
    const int n0 = blockIdx.x * BN;

    for (int k0 = 0; k0 < Kdim; k0 += BK) {
        // ---- load A tile (transposed into smem: As[k][m]) ----
        constexpr int A4 = BM * BK / 4;
#pragma unroll
        for (int i = tid; i < A4; i += THREADS) {
            const int r = i / (BK / 4);
            const int c = (i % (BK / 4)) * 4;
            float4 v = *reinterpret_cast<const float4*>(
                A + (size_t)(m0 + r) * Kdim + k0 + c);
            As[c + 0][r] = v.x; As[c + 1][r] = v.y;
            As[c + 2][r] = v.z; As[c + 3][r] = v.w;
        }
        // ---- load B tile ----
        if (TRANSB) {
            constexpr int B4 = BN * BK / 4;
#pragma unroll
            for (int i = tid; i < B4; i += THREADS) {
                const int r = i / (BK / 4);
                const int c = (i % (BK / 4)) * 4;
                float4 v = *reinterpret_cast<const float4*>(
                    B + (size_t)(n0 + r) * Kdim + k0 + c);
                Bs[c + 0][r] = v.x; Bs[c + 1][r] = v.y;
                Bs[c + 2][r] = v.z; Bs[c + 3][r] = v.w;
            }
        } else {
            constexpr int B4 = BK * BN / 4;
#pragma unroll
            for (int i = tid; i < B4; i += THREADS) {
                const int r = i / (BN / 4);
                const int c = (i % (BN / 4)) * 4;
                float4 v = *reinterpret_cast<const float4*>(
                    B + (size_t)(k0 + r) * Ndim + n0 + c);
                *reinterpret_cast<float4*>(&Bs[r][c]) = v;
            }
        }
        __syncthreads();

        // ---- compute ----
#pragma unroll
        for (int k = 0; k < BK; ++k) {
            float a[TM], b[TN];
#pragma unroll
            for (int i = 0; i < TM; i += 4) {
                float4 v = *reinterpret_cast<const float4*>(&As[k][ty * TM + i]);
                a[i] = v.x; a[i + 1] = v.y; a[i + 2] = v.z; a[i + 3] = v.w;
            }
#pragma unroll
            for (int j = 0; j < TN; j += 4) {
                float4 v = *reinterpret_cast<const float4*>(&Bs[k][tx * TN + j]);
                b[j] = v.x; b[j + 1] = v.y; b[j + 2] = v.z; b[j + 3] = v.w;
            }
#pragma unroll
            for (int i = 0; i < TM; ++i)
#pragma unroll
                for (int j = 0; j < TN; ++j) acc[i][j] = fmaf(a[i], b[j], acc[i][j]);
        }
        __syncthreads();
    }

    // ---- epilogue ----
#pragma unroll
    for (int i = 0; i < TM; ++i) {
        const int m = m0 + ty * TM + i;
#pragma unroll
        for (int j = 0; j < TN; ++j) {
            const int n = n0 + tx * TN + j;
            float v = acc[i][j];
            if (MODE == 0) {
                v += bias[n] + extra[(size_t)m * Ndim + n];
                C[(size_t)m * Ndim + n] = v;
            } else if (MODE == 1) {
                v = (v + bias[n]) * scale;
                const int bb = m / Sq, s = m % Sq;
                const int h = n / HDq, d = n % HDq;
                C[(((size_t)bb * NHq + h) * Sq + s) * HDq + d] = v;
            } else if (MODE == 2) {
                const int bb = bz / NHq;
                v += extra[(size_t)bb * Sq + n];
                C[(size_t)bz * strideC + (size_t)m * Ndim + n] = v;
            } else {  // MODE 3
                const int bb = bz / NHq, h = bz % NHq;
                C[(size_t)bb * Sq * Hq + (size_t)m * Hq + (size_t)h * HDq + n] = v;
            }
        }
    }
}

// ---------------------------------------------------------------------------
// Row softmax over 2048 elements; 256 threads, 8 elems/thread kept in regs.
// ---------------------------------------------------------------------------
__global__ __launch_bounds__(256) void softmax_k(float* __restrict__ p) {
    const size_t row = blockIdx.x;
    float* r = p + row * (size_t)Sq;
    const int tid = threadIdx.x;

    float4 v0 = reinterpret_cast<const float4*>(r)[tid];
    float4 v1 = reinterpret_cast<const float4*>(r)[tid + 256];

    float m = fmaxf(fmaxf(fmaxf(v0.x, v0.y), fmaxf(v0.z, v0.w)),
                    fmaxf(fmaxf(v1.x, v1.y), fmaxf(v1.z, v1.w)));

    __shared__ float red[256];
    red[tid] = m; __syncthreads();
    for (int off = 128; off > 0; off >>= 1) {
        if (tid < off) red[tid] = fmaxf(red[tid], red[tid + off]);
        __syncthreads();
    }
    const float rowmax = red[0];
    __syncthreads();

    v0.x = expf(v0.x - rowmax); v0.y = expf(v0.y - rowmax);
    v0.z = expf(v0.z - rowmax); v0.w = expf(v0.w - rowmax);
    v1.x = expf(v1.x - rowmax); v1.y = expf(v1.y - rowmax);
    v1.z = expf(v1.z - rowmax); v1.w = expf(v1.w - rowmax);

    float s = v0.x + v0.y + v0.z + v0.w + v1.x + v1.y + v1.z + v1.w;
    red[tid] = s; __syncthreads();
    for (int off = 128; off > 0; off >>= 1) {
        if (tid < off) red[tid] += red[tid + off];
        __syncthreads();
    }
    const float inv = 1.0f / red[0];

    v0.x *= inv; v0.y *= inv; v0.z *= inv; v0.w *= inv;
    v1.x *= inv; v1.y *= inv; v1.z *= inv; v1.w *= inv;
    reinterpret_cast<float4*>(r)[tid]       = v0;
    reinterpret_cast<float4*>(r)[tid + 256] = v1;
}

// ---------------------------------------------------------------------------
// Launch
// ---------------------------------------------------------------------------
extern "C" void kernel_launch(void* const* d_in, const int* in_sizes, int n_in,
                              void* d_out, int out_size) {
    const float* hs    = (const float*)d_in[0];
    const float* mask  = (const float*)d_in[1];
    const float* wq    = (const float*)d_in[2];
    const float* bq    = (const float*)d_in[3];
    const float* wk    = (const float*)d_in[4];
    const float* bk    = (const float*)d_in[5];
    const float* wv    = (const float*)d_in[6];
    const float* bv    = (const float*)d_in[7];
    const float* wo    = (const float*)d_in[8];
    const float* bo    = (const float*)d_in[9];
    const float* gam   = (const float*)d_in[10];
    const float* bet   = (const float*)d_in[11];
    float* out = (float*)d_out;

    float *xln, *q, *k, *v, *sc, *ctx;
    cudaGetSymbolAddress((void**)&xln, g_xln);
    cudaGetSymbolAddress((void**)&q,   g_q);
    cudaGetSymbolAddress((void**)&k,   g_k);
    cudaGetSymbolAddress((void**)&v,   g_v);
    cudaGetSymbolAddress((void**)&sc,  g_sc);
    cudaGetSymbolAddress((void**)&ctx, g_ctx);

    // 1) LayerNorm
    ln_k<<<Mq, 256>>>(hs, gam, bet, xln);

    // 2) QKV projections (NT GEMM, head-layout epilogue; Q pre-scaled by 1/8)
    gemm_k<128, 128, 16, 8, 8, true, 1>
        <<<dim3(Hq / 128, Mq / 128, 1), 256>>>(xln, wq, bq, nullptr, q,
                                               Mq, Hq, Hq, 0, 0, 0, 0.125f);
    gemm_k<128, 128, 16, 8, 8, true, 1>
        <<<dim3(Hq / 128, Mq / 128, 1), 256>>>(xln, wk, bk, nullptr, k,
                                               Mq, Hq, Hq, 0, 0, 0, 1.0f);
    gemm_k<128, 128, 16, 8, 8, true, 1>
        <<<dim3(Hq / 128, Mq / 128, 1), 256>>>(xln, wv, bv, nullptr, v,
                                               Mq, Hq, Hq, 0, 0, 0, 1.0f);

    // 3) scores = Q K^T (+ mask), batched over B*NH = 32
    gemm_k<128, 128, 16, 8, 8, true, 2>
        <<<dim3(Sq / 128, Sq / 128, Bq * NHq), 256>>>(
            q, k, nullptr, mask, sc, Sq, Sq, HDq,
            (long)Sq * HDq, (long)Sq * HDq, (long)Sq * Sq, 1.0f);

    // 4) softmax over rows
    softmax_k<<<Bq * NHq * Sq, 256>>>(sc);

    // 5) ctx = P V (NN GEMM, batched), scatter into [B,S,H]
    gemm_k<128, 64, 16, 8, 8, false, 3>
        <<<dim3(1, Sq / 128, Bq * NHq), 128>>>(
            sc, v, nullptr, nullptr, ctx, Sq, HDq, Sq,
            (long)Sq * Sq, (long)Sq * HDq, 0, 1.0f);

    // 6) out = ctx Wo^T + bo + residual
    gemm_k<128, 128, 16, 8, 8, true, 0>
        <<<dim3(Hq / 128, Mq / 128, 1), 256>>>(ctx, wo, bo, hs, out,
                                               Mq, Hq, Hq, 0, 0, 0, 1.0f);
}

// round 4
// speedup vs baseline: 2.8179x; 2.8179x over previous
#include <cuda_runtime.h>
#include <cstdint>

// Problem constants
#define Bq 2
#define Sq 2048
#define Hq 1024
#define NHq 16
#define HDq 64
#define Mq (Bq * Sq)   // 4096

// ---------------------------------------------------------------------------
// Scratch (device globals — no allocation allowed)
// ---------------------------------------------------------------------------
__device__ float g_xln[(size_t)Mq * Hq];                       // 16 MB
__device__ float g_q[(size_t)Mq * Hq];                         // 16 MB  [B,NH,S,HD]
__device__ float g_k[(size_t)Mq * Hq];                         // 16 MB  [B,NH,S,HD]
__device__ float g_v[(size_t)Mq * Hq];                         // 16 MB  [B,NH,HD,S] (transposed!)
__device__ float g_sc[(size_t)Bq * NHq * Sq * Sq];             // 512 MB
__device__ float g_ctx[(size_t)Mq * Hq];                       // 16 MB

// ---------------------------------------------------------------------------
// Portable PTX helpers (sm_80-level features only — no tcgen05 on this target)
// ---------------------------------------------------------------------------
__device__ __forceinline__ uint32_t smem_to_u32(const void* p) {
    uint32_t a;
    asm("{ .reg .u64 t; cvta.to.shared.u64 t, %1; cvt.u32.u64 %0, t; }" : "=r"(a) : "l"(p));
    return a;
}
__device__ __forceinline__ void cp_async16(uint32_t dst, const void* src) {
    asm volatile("cp.async.cg.shared.global [%0], [%1], 16;" :: "r"(dst), "l"(src));
}
__device__ __forceinline__ void ldsm4(uint32_t& r0, uint32_t& r1, uint32_t& r2,
                                      uint32_t& r3, uint32_t addr) {
    asm volatile("ldmatrix.sync.aligned.m8n8.x4.shared.b16 {%0,%1,%2,%3}, [%4];"
                 : "=r"(r0), "=r"(r1), "=r"(r2), "=r"(r3) : "r"(addr));
}
__device__ __forceinline__ void mma_tf32(float* c, const uint32_t* a, const uint32_t* b) {
    asm volatile("mma.sync.aligned.m16n8k8.row.col.f32.tf32.tf32.f32 "
                 "{%0,%1,%2,%3}, {%4,%5,%6,%7}, {%8,%9}, {%0,%1,%2,%3};"
                 : "+f"(c[0]), "+f"(c[1]), "+f"(c[2]), "+f"(c[3])
                 : "r"(a[0]), "r"(a[1]), "r"(a[2]), "r"(a[3]), "r"(b[0]), "r"(b[1]));
}
__device__ __forceinline__ void cvt_tf32(uint32_t& x) {
    asm("cvt.rna.tf32.f32 %0, %0;" : "+r"(x));
}

// ---------------------------------------------------------------------------
// LayerNorm: one block per row (4096 rows, H=1024), 256 threads x 4 floats
// ---------------------------------------------------------------------------
__global__ __launch_bounds__(256) void ln_k(const float* __restrict__ x,
                                            const float* __restrict__ gamma,
                                            const float* __restrict__ beta,
                                            float* __restrict__ out) {
    const int row = blockIdx.x;
    const int tid = threadIdx.x;
    const float* xr = x + (size_t)row * Hq;

    float4 v = reinterpret_cast<const float4*>(xr)[tid];
    float s  = v.x + v.y + v.z + v.w;
    float ss = v.x * v.x + v.y * v.y + v.z * v.z + v.w * v.w;

    __shared__ float red[256];
    red[tid] = s; __syncthreads();
    for (int off = 128; off > 0; off >>= 1) {
        if (tid < off) red[tid] += red[tid + off];
        __syncthreads();
    }
    const float mean = red[0] * (1.0f / Hq);
    __syncthreads();
    red[tid] = ss; __syncthreads();
    for (int off = 128; off > 0; off >>= 1) {
        if (tid < off) red[tid] += red[tid + off];
        __syncthreads();
    }
    const float var  = red[0] * (1.0f / Hq) - mean * mean;
    const float rstd = rsqrtf(var + 1e-12f);

    float4 g = reinterpret_cast<const float4*>(gamma)[tid];
    float4 b = reinterpret_cast<const float4*>(beta)[tid];
    float4 o;
    o.x = (v.x - mean) * rstd * g.x + b.x;
    o.y = (v.y - mean) * rstd * g.y + b.y;
    o.z = (v.z - mean) * rstd * g.z + b.z;
    o.w = (v.w - mean) * rstd * g.w + b.w;
    reinterpret_cast<float4*>(out + (size_t)row * Hq)[tid] = o;
}

// ---------------------------------------------------------------------------
// tf32 mma.sync NT GEMM:  C_tile[128, BN] = A[M,K] * B[N,K]^T (both K-major)
// 3-stage cp.async pipeline, SW128-swizzled K-major smem tiles, ldmatrix
// operand loads, m16n8k8 tf32 HMMA, fused epilogues:
//   0: out-proj : C[m*H+n] = acc + bias[n] + extra[m*H+n]
//   1: Q/K proj : v=(acc+bias[n])*scale -> [B,NH,S,HD]
//   2: scores   : v=acc + mask[bb*S+n]  -> C + bz*strideC, row stride S
//   3: ctx (PV) : v=acc -> ctx[bb, m, h*HD+n]
//   4: V proj   : v=acc+bias[n]        -> [B,NH,HD,S]  (transposed V)
// ---------------------------------------------------------------------------
template <int BN, int MODE>
__global__ __launch_bounds__(256)
void wmma_k(const float* __restrict__ A, const float* __restrict__ B,
            const float* __restrict__ bias, const float* __restrict__ extra,
            float* __restrict__ C, int Kdim,
            long strideA, long strideB, long strideC, float scale) {
    constexpr int STAGES = 3;
    constexpr int ASZ = 128 * 128;          // bytes: 128 rows x 32 floats
    constexpr int BSZ = BN * 128;
    constexpr int STG = ASZ + BSZ;
    constexpr int WGM = (BN == 128) ? 2 : 4;
    constexpr int WGN = 8 / WGM;
    constexpr int WM  = 128 / WGM;          // 64 or 32
    constexpr int WN  = BN / WGN;           // 32
    constexpr int MT  = WM / 16;
    constexpr int NT  = WN / 8;
    constexpr int NA4 = 4;                  // A float4 loads per thread per chunk
    constexpr int NB4 = BN / 32;            // B float4 loads per thread per chunk

    extern __shared__ char smem[];
    const uint32_t sbase = smem_to_u32(smem);

    const int tid  = threadIdx.x;
    const int wid  = tid >> 5;
    const int lane = tid & 31;
    const int bz   = blockIdx.z;
    const int m0   = blockIdx.y * 128;
    const int n0   = blockIdx.x * BN;

    A += (size_t)bz * strideA;
    B += (size_t)bz * strideB;

    const int wm0 = (wid % WGM) * WM;
    const int wn0 = (wid / WGM) * WN;

    const int KT = Kdim >> 5;

    auto issue = [&](int kt) {
        const uint32_t abase = sbase + (uint32_t)(kt % STAGES) * STG;
        const float* Ak = A + (size_t)kt * 32;
#pragma unroll
        for (int i = 0; i < NA4; ++i) {
            const int idx = tid + i * 256, r = idx >> 3, c = idx & 7;
            const uint32_t dst = abase + r * 128 + ((c * 16) ^ ((r & 7) << 4));
            cp_async16(dst, Ak + (size_t)(m0 + r) * Kdim + c * 4);
        }
        const uint32_t bbase = abase + ASZ;
        const float* Bk = B + (size_t)kt * 32;
#pragma unroll
        for (int i = 0; i < NB4; ++i) {
            const int idx = tid + i * 256, r = idx >> 3, c = idx & 7;
            const uint32_t dst = bbase + r * 128 + ((c * 16) ^ ((r & 7) << 4));
            cp_async16(dst, Bk + (size_t)(n0 + r) * Kdim + c * 4);
        }
    };

    float acc[MT][NT][4];
#pragma unroll
    for (int i = 0; i < MT; ++i)
#pragma unroll
        for (int j = 0; j < NT; ++j)
#pragma unroll
            for (int e = 0; e < 4; ++e) acc[i][j][e] = 0.0f;

    // ldmatrix per-thread address components
    const int a_ri = (lane & 7) + ((lane >> 3) & 1) * 8;   // row within A m-tile
    const int a_ko = ((lane >> 4) & 1) * 16;               // k-byte offset
    const int b_ri = (lane & 7) + ((lane >> 4) & 1) * 8;   // row within B n-pair
    const int b_ko = ((lane >> 3) & 1) * 16;

    // prologue
    for (int kt = 0; kt < STAGES - 1 && kt < KT; ++kt) {
        issue(kt);
        asm volatile("cp.async.commit_group;" ::: "memory");
    }

    for (int kt = 0; kt < KT; ++kt) {
        asm volatile("cp.async.wait_group %0;" :: "n"(STAGES - 2) : "memory");
        __syncthreads();
        if (kt + STAGES - 1 < KT) issue(kt + STAGES - 1);
        asm volatile("cp.async.commit_group;" ::: "memory");

        const uint32_t abase = sbase + (uint32_t)(kt % STAGES) * STG;
        const uint32_t bbase = abase + ASZ;
#pragma unroll
        for (int ks = 0; ks < 4; ++ks) {
            uint32_t af[MT][4], bf[NT][2];
#pragma unroll
            for (int mt = 0; mt < MT; ++mt) {
                const int row = wm0 + mt * 16 + a_ri;
                const int kb  = ks * 32 + a_ko;
                ldsm4(af[mt][0], af[mt][1], af[mt][2], af[mt][3],
                      abase + row * 128 + (kb ^ ((row & 7) << 4)));
            }
#pragma unroll
            for (int np = 0; np < NT / 2; ++np) {
                const int row = wn0 + np * 16 + b_ri;
                const int kb  = ks * 32 + b_ko;
                ldsm4(bf[2 * np][0], bf[2 * np][1], bf[2 * np + 1][0], bf[2 * np + 1][1],
                      bbase + row * 128 + (kb ^ ((row & 7) << 4)));
            }
#pragma unroll
            for (int mt = 0; mt < MT; ++mt)
#pragma unroll
                for (int e = 0; e < 4; ++e) cvt_tf32(af[mt][e]);
#pragma unroll
            for (int nt = 0; nt < NT; ++nt) {
                cvt_tf32(bf[nt][0]); cvt_tf32(bf[nt][1]);
            }
#pragma unroll
            for (int mt = 0; mt < MT; ++mt)
#pragma unroll
                for (int nt = 0; nt < NT; ++nt)
                    mma_tf32(acc[mt][nt], af[mt], bf[nt]);
        }
    }

    // ---- epilogue ----
    const int g = lane >> 2, tig = lane & 3;
#pragma unroll
    for (int mt = 0; mt < MT; ++mt) {
#pragma unroll
        for (int half = 0; half < 2; ++half) {
            const int m = m0 + wm0 + mt * 16 + g + half * 8;
#pragma unroll
            for (int nt = 0; nt < NT; ++nt) {
                const int n = n0 + wn0 + nt * 8 + 2 * tig;
                const float c0 = acc[mt][nt][half * 2 + 0];
                const float c1 = acc[mt][nt][half * 2 + 1];
                if (MODE == 0) {
                    const float2 bi = *reinterpret_cast<const float2*>(bias + n);
                    const float2 ex = *reinterpret_cast<const float2*>(extra + (size_t)m * Hq + n);
                    float2 o; o.x = c0 + bi.x + ex.x; o.y = c1 + bi.y + ex.y;
                    *reinterpret_cast<float2*>(C + (size_t)m * Hq + n) = o;
                } else if (MODE == 1) {
                    const float2 bi = *reinterpret_cast<const float2*>(bias + n);
                    const int bb = m >> 11, sI = m & (Sq - 1);
                    const int h = n >> 6, d = n & 63;
                    float2 o; o.x = (c0 + bi.x) * scale; o.y = (c1 + bi.y) * scale;
                    *reinterpret_cast<float2*>(
                        C + (((size_t)bb * NHq + h) * Sq + sI) * HDq + d) = o;
                } else if (MODE == 2) {
                    const int bb = bz / NHq;
                    const float2 mk = *reinterpret_cast<const float2*>(extra + (size_t)bb * Sq + n);
                    float2 o; o.x = c0 + mk.x; o.y = c1 + mk.y;
                    *reinterpret_cast<float2*>(C + (size_t)bz * strideC + (size_t)m * Sq + n) = o;
                } else if (MODE == 3) {
                    const int bb = bz >> 4, h = bz & 15;
                    float2 o; o.x = c0; o.y = c1;
                    *reinterpret_cast<float2*>(
                        C + (size_t)bb * Sq * Hq + (size_t)m * Hq + h * HDq + n) = o;
                } else {  // MODE 4: V transposed [B,NH,HD,S]
                    const int bb = m >> 11, sI = m & (Sq - 1);
                    const int h = n >> 6, d = n & 63;
                    float* dst = C + (((size_t)bb * NHq + h) * HDq + d) * Sq + sI;
                    dst[0]  = c0 + bias[n];
                    dst[Sq] = c1 + bias[n + 1];
                }
            }
        }
    }
}

// ---------------------------------------------------------------------------
// Row softmax over 2048 elements; 256 threads, 8 elems/thread in regs.
// ---------------------------------------------------------------------------
__global__ __launch_bounds__(256) void softmax_k(float* __restrict__ p) {
    const size_t row = blockIdx.x;
    float* r = p + row * (size_t)Sq;
    const int tid = threadIdx.x;

    float4 v0 = reinterpret_cast<const float4*>(r)[tid];
    float4 v1 = reinterpret_cast<const float4*>(r)[tid + 256];

    float m = fmaxf(fmaxf(fmaxf(v0.x, v0.y), fmaxf(v0.z, v0.w)),
                    fmaxf(fmaxf(v1.x, v1.y), fmaxf(v1.z, v1.w)));

    __shared__ float red[256];
    red[tid] = m; __syncthreads();
    for (int off = 128; off > 0; off >>= 1) {
        if (tid < off) red[tid] = fmaxf(red[tid], red[tid + off]);
        __syncthreads();
    }
    const float rowmax = red[0];
    __syncthreads();

    v0.x = expf(v0.x - rowmax); v0.y = expf(v0.y - rowmax);
    v0.z = expf(v0.z - rowmax); v0.w = expf(v0.w - rowmax);
    v1.x = expf(v1.x - rowmax); v1.y = expf(v1.y - rowmax);
    v1.z = expf(v1.z - rowmax); v1.w = expf(v1.w - rowmax);

    float s = v0.x + v0.y + v0.z + v0.w + v1.x + v1.y + v1.z + v1.w;
    red[tid] = s; __syncthreads();
    for (int off = 128; off > 0; off >>= 1) {
        if (tid < off) red[tid] += red[tid + off];
        __syncthreads();
    }
    const float inv = 1.0f / red[0];

    v0.x *= inv; v0.y *= inv; v0.z *= inv; v0.w *= inv;
    v1.x *= inv; v1.y *= inv; v1.z *= inv; v1.w *= inv;
    reinterpret_cast<float4*>(r)[tid]       = v0;
    reinterpret_cast<float4*>(r)[tid + 256] = v1;
}

// ---------------------------------------------------------------------------
// Launch
// ---------------------------------------------------------------------------
extern "C" void kernel_launch(void* const* d_in, const int* in_sizes, int n_in,
                              void* d_out, int out_size) {
    const float* hs   = (const float*)d_in[0];
    const float* mask = (const float*)d_in[1];
    const float* wq   = (const float*)d_in[2];
    const float* bq   = (const float*)d_in[3];
    const float* wk   = (const float*)d_in[4];
    const float* bk   = (const float*)d_in[5];
    const float* wv   = (const float*)d_in[6];
    const float* bv   = (const float*)d_in[7];
    const float* wo   = (const float*)d_in[8];
    const float* bo   = (const float*)d_in[9];
    const float* gam  = (const float*)d_in[10];
    const float* bet  = (const float*)d_in[11];
    float* out = (float*)d_out;

    float *xln, *q, *k, *v, *sc, *ctx;
    cudaGetSymbolAddress((void**)&xln, g_xln);
    cudaGetSymbolAddress((void**)&q,   g_q);
    cudaGetSymbolAddress((void**)&k,   g_k);
    cudaGetSymbolAddress((void**)&v,   g_v);
    cudaGetSymbolAddress((void**)&sc,  g_sc);
    cudaGetSymbolAddress((void**)&ctx, g_ctx);

    constexpr int SM128 = 3 * (128 * 128 + 128 * 128);  // 98304
    constexpr int SM64  = 3 * (128 * 128 + 64 * 128);   // 73728
    cudaFuncSetAttribute((const void*)wmma_k<128, 0>, cudaFuncAttributeMaxDynamicSharedMemorySize, SM128);
    cudaFuncSetAttribute((const void*)wmma_k<128, 1>, cudaFuncAttributeMaxDynamicSharedMemorySize, SM128);
    cudaFuncSetAttribute((const void*)wmma_k<128, 2>, cudaFuncAttributeMaxDynamicSharedMemorySize, SM128);
    cudaFuncSetAttribute((const void*)wmma_k<128, 4>, cudaFuncAttributeMaxDynamicSharedMemorySize, SM128);
    cudaFuncSetAttribute((const void*)wmma_k<64, 3>,  cudaFuncAttributeMaxDynamicSharedMemorySize, SM64);

    // 1) LayerNorm
    ln_k<<<Mq, 256>>>(hs, gam, bet, xln);

    // 2) QKV projections (NT, K=1024). Q scaled by 1/8; V written transposed.
    wmma_k<128, 1><<<dim3(Hq / 128, Mq / 128, 1), 256, SM128>>>(
        xln, wq, bq, nullptr, q, Hq, 0, 0, 0, 0.125f);
    wmma_k<128, 1><<<dim3(Hq / 128, Mq / 128, 1), 256, SM128>>>(
        xln, wk, bk, nullptr, k, Hq, 0, 0, 0, 1.0f);
    wmma_k<128, 4><<<dim3(Hq / 128, Mq / 128, 1), 256, SM128>>>(
        xln, wv, bv, nullptr, v, Hq, 0, 0, 0, 1.0f);

    // 3) scores = Q K^T (+ mask), batched over B*NH=32, K=64
    wmma_k<128, 2><<<dim3(Sq / 128, Sq / 128, Bq * NHq), 256, SM128>>>(
        q, k, nullptr, mask, sc, HDq,
        (long)Sq * HDq, (long)Sq * HDq, (long)Sq * Sq, 1.0f);

    // 4) softmax over rows
    softmax_k<<<Bq * NHq * Sq, 256>>>(sc);

    // 5) ctx = P V  (NT with transposed V, K=2048)
    wmma_k<64, 3><<<dim3(1, Sq / 128, Bq * NHq), 256, SM64>>>(
        sc, v, nullptr, nullptr, ctx, Sq,
        (long)Sq * Sq, (long)HDq * Sq, 0, 1.0f);

    // 6) out = ctx Wo^T + bo + residual
    wmma_k<128, 0><<<dim3(Hq / 128, Mq / 128, 1), 256, SM128>>>(
        ctx, wo, bo, hs, out, Hq, 0, 0, 0, 1.0f);
}